// round 6
// baseline (speedup 1.0000x reference)
#include <cuda_runtime.h>
#include <cuda_bf16.h>
#include <cstdint>

#define NN 100000   // nodes per type
#define EE 600000   // edges per relation
#define DD 128      // hidden dim
#define NB2 196     // scan blocks: ceil(2*NN/1024)

// ---------------- scratch (static device globals) ----------------
// Packed bf16x2 hi/lo planes for GEMM input (reused: x_user first, then u1)
__device__ uint32_t g_xh[(size_t)NN * 64];
__device__ uint32_t g_xl[(size_t)NN * 64];
__device__ uint32_t g_wh[3][128 * 64];    // pre-split W^T planes (n-major)
__device__ uint32_t g_wl[3][128 * 64];
__device__ float    g_yf[(size_t)NN * DD];
__device__ float    g_yr[(size_t)NN * DD];
__device__ int      g_cnt[2 * NN];        // combined histogram / cursor
__device__ int      g_rowptr[2 * NN + 1]; // combined CSC row pointers
__device__ int      g_perm[2 * EE];       // combined src ids sorted by (rel,dst)
__device__ int      g_part[NB2];          // scan partials

// ---------------- bf16 hi/lo split helpers ----------------
__device__ __forceinline__ uint32_t pack2(__nv_bfloat16 lo, __nv_bfloat16 hi)
{
    return (uint32_t)__bfloat16_as_ushort(lo) | ((uint32_t)__bfloat16_as_ushort(hi) << 16);
}

__device__ __forceinline__ void split2(float x, float y, uint32_t& h, uint32_t& l)
{
    __nv_bfloat16 hx = __float2bfloat16_rn(x);
    __nv_bfloat16 hy = __float2bfloat16_rn(y);
    __nv_bfloat16 lx = __float2bfloat16_rn(x - __bfloat162float(hx));
    __nv_bfloat16 ly = __float2bfloat16_rn(y - __bfloat162float(hy));
    h = pack2(hx, hy);
    l = pack2(lx, ly);
}

// ===================== presplit kernels =====================
// X[n,128] fp32 -> hi/lo planes [n][64] u32 (bf16x2, low half = even k)
__global__ __launch_bounds__(256) void presplit_x(
    const float* __restrict__ X, uint32_t* __restrict__ Xh,
    uint32_t* __restrict__ Xl, int n)
{
    int idx = blockIdx.x * blockDim.x + threadIdx.x;
    if (idx >= n * 32) return;
    int r = idx >> 5, L = idx & 31;
    float4 v = reinterpret_cast<const float4*>(X)[(size_t)r * 32 + L];
    uint32_t h0, l0, h1, l1;
    split2(v.x, v.y, h0, l0);
    split2(v.z, v.w, h1, l1);
    *reinterpret_cast<uint2*>(Xh + (size_t)r * 64 + 2 * L) = make_uint2(h0, h1);
    *reinterpret_cast<uint2*>(Xl + (size_t)r * 64 + 2 * L) = make_uint2(l0, l1);
}

// W[k,n] fp32 -> W^T hi/lo planes [n][64] u32
__global__ __launch_bounds__(256) void presplit_w(
    const float* __restrict__ W, uint32_t* __restrict__ Wh, uint32_t* __restrict__ Wl)
{
    int idx = blockIdx.x * blockDim.x + threadIdx.x;   // 0..8191
    if (idx >= 128 * 64) return;
    int n = idx & 127, kp = idx >> 7;
    float w0 = W[(size_t)(2 * kp) * DD + n];
    float w1 = W[(size_t)(2 * kp + 1) * DD + n];
    uint32_t h, l;
    split2(w0, w1, h, l);
    Wh[n * 64 + kp] = h;
    Wl[n * 64 + kp] = l;
}

// ===================== combined CSC build (both relations) =====================
__global__ void hist2_kernel(const int* __restrict__ dst_f, const int* __restrict__ dst_r,
                             int* __restrict__ cnt)
{
    int e = blockIdx.x * blockDim.x + threadIdx.x;
    if (e < EE)            atomicAdd(&cnt[dst_f[e]], 1);
    else if (e < 2 * EE)   atomicAdd(&cnt[NN + dst_r[e - EE]], 1);
}

__global__ __launch_bounds__(1024) void block_reduce(
    const int* __restrict__ cnt, int* __restrict__ part, int n)
{
    __shared__ int s[1024];
    int t = threadIdx.x;
    int idx = blockIdx.x * 1024 + t;
    s[t] = (idx < n) ? cnt[idx] : 0;
    __syncthreads();
#pragma unroll
    for (int off = 512; off > 0; off >>= 1) {
        if (t < off) s[t] += s[t + off];
        __syncthreads();
    }
    if (t == 0) part[blockIdx.x] = s[0];
}

__global__ __launch_bounds__(256) void scan_partials(int* __restrict__ part, int nb)
{
    __shared__ int s[256];
    int t = threadIdx.x;
    int v = (t < nb) ? part[t] : 0;
    s[t] = v;
    __syncthreads();
#pragma unroll
    for (int off = 1; off < 256; off <<= 1) {
        int x = (t >= off) ? s[t - off] : 0;
        __syncthreads();
        s[t] += x;
        __syncthreads();
    }
    if (t < nb) part[t] = s[t] - v;   // exclusive
}

__global__ __launch_bounds__(1024) void block_scan_write(
    const int* __restrict__ cnt, const int* __restrict__ part,
    int* __restrict__ rowptr, int* __restrict__ cursor, int n, int total)
{
    __shared__ int s[1024];
    int t = threadIdx.x;
    int idx = blockIdx.x * 1024 + t;
    int v = (idx < n) ? cnt[idx] : 0;
    s[t] = v;
    __syncthreads();
#pragma unroll
    for (int off = 1; off < 1024; off <<= 1) {
        int x = (t >= off) ? s[t - off] : 0;
        __syncthreads();
        s[t] += x;
        __syncthreads();
    }
    int excl = s[t] - v + part[blockIdx.x];
    if (idx < n) { rowptr[idx] = excl; cursor[idx] = excl; }
    if (idx == 0) rowptr[n] = total;
}

__global__ void fill2_kernel(const int* __restrict__ src_f, const int* __restrict__ dst_f,
                             const int* __restrict__ src_r, const int* __restrict__ dst_r,
                             int* __restrict__ cursor, int* __restrict__ perm)
{
    int e = blockIdx.x * blockDim.x + threadIdx.x;
    int s, d;
    if (e < EE)          { s = src_f[e];      d = dst_f[e]; }
    else if (e < 2 * EE) { s = src_r[e - EE]; d = NN + dst_r[e - EE]; }
    else return;
    int p = atomicAdd(&cursor[d], 1);
    perm[p] = s;
}

// ===================== gathers (atomic-free segment sum) =====================
// One warp per dst node. MLP-batched: 8 independent loads in flight.
template <bool WRITE_PLANES>
__global__ __launch_bounds__(256) void gather_rows_t(
    const float* __restrict__ Y, const int* __restrict__ rowptr,
    const int* __restrict__ perm, float* __restrict__ outF,
    uint32_t* __restrict__ outH, uint32_t* __restrict__ outL, int n)
{
    int w    = (int)((blockIdx.x * (unsigned)blockDim.x + threadIdx.x) >> 5);
    int lane = threadIdx.x & 31;
    if (w >= n) return;

    int beg = __ldg(rowptr + w);
    int end = __ldg(rowptr + w + 1);

    const float4* Yv = reinterpret_cast<const float4*>(Y);
    float4 acc0 = make_float4(0.f, 0.f, 0.f, 0.f);
    float4 acc1 = make_float4(0.f, 0.f, 0.f, 0.f);

    for (int j0 = beg; j0 < end; j0 += 32) {
        int j  = j0 + lane;
        int sl = (j < end) ? __ldg(perm + j) : 0;
        int m  = min(32, end - j0);
        for (int t0 = 0; t0 < m; t0 += 8) {
            float4 v[8];
#pragma unroll
            for (int u = 0; u < 8; u++) {
                int s = __shfl_sync(0xffffffffu, sl, t0 + u);
                v[u] = (t0 + u < m) ? Yv[(size_t)s * 32 + lane]
                                    : make_float4(0.f, 0.f, 0.f, 0.f);
            }
#pragma unroll
            for (int u = 0; u < 8; u += 2) {
                acc0.x += v[u].x;     acc0.y += v[u].y;
                acc0.z += v[u].z;     acc0.w += v[u].w;
                acc1.x += v[u + 1].x; acc1.y += v[u + 1].y;
                acc1.z += v[u + 1].z; acc1.w += v[u + 1].w;
            }
        }
    }
    acc0.x += acc1.x; acc0.y += acc1.y; acc0.z += acc1.z; acc0.w += acc1.w;

    if (WRITE_PLANES) {
        uint32_t h0, l0, h1, l1;
        split2(acc0.x, acc0.y, h0, l0);
        split2(acc0.z, acc0.w, h1, l1);
        *reinterpret_cast<uint2*>(outH + (size_t)w * 64 + 2 * lane) = make_uint2(h0, h1);
        *reinterpret_cast<uint2*>(outL + (size_t)w * 64 + 2 * lane) = make_uint2(l0, l1);
    } else {
        reinterpret_cast<float4*>(outF)[(size_t)w * 32 + lane] = acc0;
    }
}

// ===================== 3xBF16 tensor-core GEMM (pre-split planes) ============
//   Y[n_rows,128] = relu(X @ W + b), inputs already split to bf16x2 hi/lo.
// CTA 128x128, 8 warps (2x4), warp tile 64x32, mma.m16n8k16.bf16.
// Staging is pure uint4 copies; smem stride 36 -> conflict-free fragment LDS.
#define PS2 36

__device__ __forceinline__ void mma_bf16(float c[4], const uint32_t a[4], const uint32_t b[2])
{
    asm volatile(
        "mma.sync.aligned.m16n8k16.row.col.f32.bf16.bf16.f32 "
        "{%0,%1,%2,%3}, {%4,%5,%6,%7}, {%8,%9}, {%0,%1,%2,%3};"
        : "+f"(c[0]), "+f"(c[1]), "+f"(c[2]), "+f"(c[3])
        : "r"(a[0]), "r"(a[1]), "r"(a[2]), "r"(a[3]), "r"(b[0]), "r"(b[1]));
}

__global__ __launch_bounds__(256, 2) void gemm_planes(
    const uint32_t* __restrict__ Xhg, const uint32_t* __restrict__ Xlg,
    const uint32_t* __restrict__ Whg, const uint32_t* __restrict__ Wlg,
    const float* __restrict__ bias, float* __restrict__ Y, int n_rows)
{
    extern __shared__ uint32_t sh[];
    uint32_t* Xh = sh;                 // [128][PS2]
    uint32_t* Xl = Xh + 128 * PS2;
    uint32_t* Wh = Xl + 128 * PS2;     // [n=128][PS2]
    uint32_t* Wl = Wh + 128 * PS2;

    const int tid  = threadIdx.x;
    const int lane = tid & 31;
    const int gid  = lane >> 2;
    const int tig  = lane & 3;
    const int wid  = tid >> 5;
    const int wm   = wid & 1;
    const int wn   = wid >> 1;
    const int row0 = blockIdx.x * 128;

    float c[4][4][4];
#pragma unroll
    for (int i = 0; i < 4; i++)
#pragma unroll
        for (int j = 0; j < 4; j++)
#pragma unroll
            for (int q = 0; q < 4; q++) c[i][j][q] = 0.f;

#pragma unroll
    for (int kc = 0; kc < 2; kc++) {
        const int kp0 = kc * 32;
        if (kc) __syncthreads();

        // ---- stage X planes: 1024 uint4 tasks per plane ----
#pragma unroll
        for (int t = 0; t < 4; t++) {
            int idx = tid + t * 256;           // 0..1023
            int r   = idx >> 3;                // 0..127
            int q   = (idx & 7) << 2;          // 0..28 (kp offset in chunk)
            uint4 vh = make_uint4(0, 0, 0, 0), vl = make_uint4(0, 0, 0, 0);
            if (row0 + r < n_rows) {
                vh = *reinterpret_cast<const uint4*>(Xhg + (size_t)(row0 + r) * 64 + kp0 + q);
                vl = *reinterpret_cast<const uint4*>(Xlg + (size_t)(row0 + r) * 64 + kp0 + q);
            }
            *reinterpret_cast<uint4*>(Xh + r * PS2 + q) = vh;
            *reinterpret_cast<uint4*>(Xl + r * PS2 + q) = vl;
        }
        // ---- stage W planes ----
#pragma unroll
        for (int t = 0; t < 4; t++) {
            int idx = tid + t * 256;
            int n   = idx >> 3;
            int q   = (idx & 7) << 2;
            *reinterpret_cast<uint4*>(Wh + n * PS2 + q) =
                *reinterpret_cast<const uint4*>(Whg + (size_t)n * 64 + kp0 + q);
            *reinterpret_cast<uint4*>(Wl + n * PS2 + q) =
                *reinterpret_cast<const uint4*>(Wlg + (size_t)n * 64 + kp0 + q);
        }
        __syncthreads();

        // ---- compute: 4 k16-steps per chunk ----
#pragma unroll
        for (int ks = 0; ks < 4; ks++) {
            const int kb = ks * 8;

            uint32_t bh[4][2], bl[4][2];
#pragma unroll
            for (int nf = 0; nf < 4; nf++) {
                int n = wn * 32 + nf * 8 + gid;
                bh[nf][0] = Wh[n * PS2 + kb + tig];
                bh[nf][1] = Wh[n * PS2 + kb + tig + 4];
                bl[nf][0] = Wl[n * PS2 + kb + tig];
                bl[nf][1] = Wl[n * PS2 + kb + tig + 4];
            }
#pragma unroll
            for (int mf = 0; mf < 4; mf++) {
                int r0 = wm * 64 + mf * 16 + gid;
                uint32_t ah[4], al[4];
                ah[0] = Xh[r0 * PS2 + kb + tig];
                ah[1] = Xh[(r0 + 8) * PS2 + kb + tig];
                ah[2] = Xh[r0 * PS2 + kb + tig + 4];
                ah[3] = Xh[(r0 + 8) * PS2 + kb + tig + 4];
                al[0] = Xl[r0 * PS2 + kb + tig];
                al[1] = Xl[(r0 + 8) * PS2 + kb + tig];
                al[2] = Xl[r0 * PS2 + kb + tig + 4];
                al[3] = Xl[(r0 + 8) * PS2 + kb + tig + 4];
#pragma unroll
                for (int nf = 0; nf < 4; nf++) {
                    mma_bf16(c[mf][nf], al, bh[nf]);
                    mma_bf16(c[mf][nf], ah, bl[nf]);
                    mma_bf16(c[mf][nf], ah, bh[nf]);
                }
            }
        }
    }

    // ---- epilogue: bias + ReLU, float2 stores ----
#pragma unroll
    for (int nf = 0; nf < 4; nf++) {
        int col = wn * 32 + nf * 8 + 2 * tig;
        float2 bb = *reinterpret_cast<const float2*>(bias + col);
#pragma unroll
        for (int mf = 0; mf < 4; mf++) {
            int row = row0 + wm * 64 + mf * 16 + gid;
            if (row < n_rows) {
                float2 o;
                o.x = fmaxf(c[mf][nf][0] + bb.x, 0.f);
                o.y = fmaxf(c[mf][nf][1] + bb.y, 0.f);
                *reinterpret_cast<float2*>(Y + (size_t)row * DD + col) = o;
            }
            if (row + 8 < n_rows) {
                float2 o;
                o.x = fmaxf(c[mf][nf][2] + bb.x, 0.f);
                o.y = fmaxf(c[mf][nf][3] + bb.y, 0.f);
                *reinterpret_cast<float2*>(Y + (size_t)(row + 8) * DD + col) = o;
            }
        }
    }
}

// ===================== launch =====================
extern "C" void kernel_launch(void* const* d_in, const int* in_sizes, int n_in,
                              void* d_out, int out_size)
{
    const float* x_user = nullptr;
    const int*   ei_f   = nullptr;
    const int*   ei_r   = nullptr;
    const float* Wm[4]  = {nullptr, nullptr, nullptr, nullptr};
    const float* bm[4]  = {nullptr, nullptr, nullptr, nullptr};
    int xcnt = 0, ecnt = 0, wcnt = 0, bcnt = 0;

    for (int i = 0; i < n_in; i++) {
        int sz = in_sizes[i];
        if (sz == NN * DD) {
            if (xcnt == 0) x_user = (const float*)d_in[i];
            xcnt++;                        // x_item is dead code in the reference
        } else if (sz == 2 * EE) {
            if (ecnt == 0) ei_f = (const int*)d_in[i];
            else           ei_r = (const int*)d_in[i];
            ecnt++;
        } else if (sz == DD * DD) {
            if (wcnt < 4) Wm[wcnt] = (const float*)d_in[i];
            wcnt++;
        } else if (sz == DD) {
            if (bcnt < 4) bm[bcnt] = (const float*)d_in[i];
            bcnt++;
        }
    }

    uint32_t *xh, *xl, *wh, *wl;
    cudaGetSymbolAddress((void**)&xh, g_xh);
    cudaGetSymbolAddress((void**)&xl, g_xl);
    cudaGetSymbolAddress((void**)&wh, g_wh);
    cudaGetSymbolAddress((void**)&wl, g_wl);
    float *yf, *yr;
    cudaGetSymbolAddress((void**)&yf, g_yf);
    cudaGetSymbolAddress((void**)&yr, g_yr);
    int *cnt, *rp, *pm, *pt;
    cudaGetSymbolAddress((void**)&cnt, g_cnt);
    cudaGetSymbolAddress((void**)&rp,  g_rowptr);
    cudaGetSymbolAddress((void**)&pm,  g_perm);
    cudaGetSymbolAddress((void**)&pt,  g_part);

    float* out_xu = (float*)d_out;
    float* out_xi = (float*)d_out + (size_t)NN * DD;

    const int* src_f = ei_f;
    const int* dst_f = ei_f + EE;
    const int* src_r = ei_r;
    const int* dst_r = ei_r + EE;

    const int eb2 = (2 * EE + 255) / 256;
    const int gb  = (NN + 7) / 8;              // warp per node, 256-thread blocks
    const int gemm_blocks = (NN + 127) / 128;
    const size_t gemm_smem = 4u * 128u * PS2 * sizeof(uint32_t);  // 73728 B

    static cudaStream_t sB = nullptr;
    static cudaEvent_t  evFork = nullptr, evBuild = nullptr;
    static bool attr_set = false;
    if (!sB) {
        cudaStreamCreateWithFlags(&sB, cudaStreamNonBlocking);
        cudaEventCreateWithFlags(&evFork,  cudaEventDisableTiming);
        cudaEventCreateWithFlags(&evBuild, cudaEventDisableTiming);
    }
    if (!attr_set) {
        cudaFuncSetAttribute(gemm_planes, cudaFuncAttributeMaxDynamicSharedMemorySize,
                             (int)gemm_smem);
        attr_set = true;
    }

    // ---- fork: side stream builds combined CSC ----
    cudaEventRecord(evFork, 0);
    cudaStreamWaitEvent(sB, evFork, 0);

    cudaMemsetAsync(cnt, 0, 2u * NN * sizeof(int), sB);
    hist2_kernel<<<eb2, 256, 0, sB>>>(dst_f, dst_r, cnt);
    block_reduce<<<NB2, 1024, 0, sB>>>(cnt, pt, 2 * NN);
    scan_partials<<<1, 256, 0, sB>>>(pt, NB2);
    block_scan_write<<<NB2, 1024, 0, sB>>>(cnt, pt, rp, cnt, 2 * NN, 2 * EE);
    fill2_kernel<<<eb2, 256, 0, sB>>>(src_f, dst_f, src_r, dst_r, cnt, pm);
    cudaEventRecord(evBuild, sB);

    // ---- main: presplit weights + x, GEMM0 ----
    presplit_w<<<32, 256, 0, 0>>>(Wm[0], wh + 0 * 8192, wl + 0 * 8192);
    presplit_w<<<32, 256, 0, 0>>>(Wm[2], wh + 1 * 8192, wl + 1 * 8192);
    presplit_w<<<32, 256, 0, 0>>>(Wm[3], wh + 2 * 8192, wl + 2 * 8192);
    presplit_x<<<(NN * 32 + 255) / 256, 256, 0, 0>>>(x_user, xh, xl, NN);

    gemm_planes<<<gemm_blocks, 256, gemm_smem, 0>>>(
        xh, xl, wh + 0 * 8192, wl + 0 * 8192, bm[0], yf, NN);

    // ---- join: gather0 needs the CSC; writes u1 directly as hi/lo planes
    //      (reuses xh/xl — GEMM0 has finished reading them by stream order) ----
    cudaStreamWaitEvent(0, evBuild, 0);
    gather_rows_t<true><<<gb, 256, 0, 0>>>(yf, rp, pm, nullptr, xh, xl, NN);

    // ---- layer 1: two GEMMs back-to-back (u1 planes stay hot in L2), then gathers ----
    gemm_planes<<<gemm_blocks, 256, gemm_smem, 0>>>(
        xh, xl, wh + 1 * 8192, wl + 1 * 8192, bm[2], yf, NN);
    gemm_planes<<<gemm_blocks, 256, gemm_smem, 0>>>(
        xh, xl, wh + 2 * 8192, wl + 2 * 8192, bm[3], yr, NN);

    gather_rows_t<false><<<gb, 256, 0, 0>>>(yf, rp,      pm, out_xu, nullptr, nullptr, NN);
    gather_rows_t<false><<<gb, 256, 0, 0>>>(yr, rp + NN, pm, out_xi, nullptr, nullptr, NN);
}

// round 8
// speedup vs baseline: 1.0917x; 1.0917x over previous
#include <cuda_runtime.h>
#include <cuda_bf16.h>
#include <cuda_fp16.h>
#include <cstdint>

#define NN 100000   // nodes per type
#define EE 600000   // edges per relation
#define DD 128      // hidden dim
#define NB2 196     // scan blocks: ceil(2*NN/1024)

// ---------------- scratch (static device globals) ----------------
__device__ float  g_yf[(size_t)NN * DD];    // layer-0 messages (fp32)
__device__ __half g_yh_f[(size_t)NN * DD];  // layer-1 'follows' messages (fp16)
__device__ __half g_yh_r[(size_t)NN * DD];  // layer-1 'rates' messages (fp16)
__device__ float  g_u1[(size_t)NN * DD];    // layer-0 user output
__device__ int    g_cnt[2 * NN];            // combined histogram / cursor
__device__ int    g_rowptr[2 * NN + 1];     // combined CSC row pointers
__device__ int    g_perm[2 * EE];           // src ids sorted by (rel,dst)
__device__ int    g_part[NB2];              // scan partials

// ===================== combined CSC build (both relations) =====================
__global__ void hist2_kernel(const int* __restrict__ dst_f, const int* __restrict__ dst_r,
                             int* __restrict__ cnt)
{
    int e = blockIdx.x * blockDim.x + threadIdx.x;
    if (e < EE)            atomicAdd(&cnt[dst_f[e]], 1);
    else if (e < 2 * EE)   atomicAdd(&cnt[NN + dst_r[e - EE]], 1);
}

__global__ __launch_bounds__(1024) void block_reduce(
    const int* __restrict__ cnt, int* __restrict__ part, int n)
{
    __shared__ int s[1024];
    int t = threadIdx.x;
    int idx = blockIdx.x * 1024 + t;
    s[t] = (idx < n) ? cnt[idx] : 0;
    __syncthreads();
#pragma unroll
    for (int off = 512; off > 0; off >>= 1) {
        if (t < off) s[t] += s[t + off];
        __syncthreads();
    }
    if (t == 0) part[blockIdx.x] = s[0];
}

__global__ __launch_bounds__(256) void scan_partials(int* __restrict__ part, int nb)
{
    __shared__ int s[256];
    int t = threadIdx.x;
    int v = (t < nb) ? part[t] : 0;
    s[t] = v;
    __syncthreads();
#pragma unroll
    for (int off = 1; off < 256; off <<= 1) {
        int x = (t >= off) ? s[t - off] : 0;
        __syncthreads();
        s[t] += x;
        __syncthreads();
    }
    if (t < nb) part[t] = s[t] - v;   // exclusive
}

__global__ __launch_bounds__(1024) void block_scan_write(
    const int* __restrict__ cnt, const int* __restrict__ part,
    int* __restrict__ rowptr, int* __restrict__ cursor, int n, int total)
{
    __shared__ int s[1024];
    int t = threadIdx.x;
    int idx = blockIdx.x * 1024 + t;
    int v = (idx < n) ? cnt[idx] : 0;
    s[t] = v;
    __syncthreads();
#pragma unroll
    for (int off = 1; off < 1024; off <<= 1) {
        int x = (t >= off) ? s[t - off] : 0;
        __syncthreads();
        s[t] += x;
        __syncthreads();
    }
    int excl = s[t] - v + part[blockIdx.x];
    if (idx < n) { rowptr[idx] = excl; cursor[idx] = excl; }
    if (idx == 0) rowptr[n] = total;
}

__global__ void fill2_kernel(const int* __restrict__ src_f, const int* __restrict__ dst_f,
                             const int* __restrict__ src_r, const int* __restrict__ dst_r,
                             int* __restrict__ cursor, int* __restrict__ perm)
{
    int e = blockIdx.x * blockDim.x + threadIdx.x;
    int s, d;
    if (e < EE)          { s = src_f[e];      d = dst_f[e]; }
    else if (e < 2 * EE) { s = src_r[e - EE]; d = NN + dst_r[e - EE]; }
    else return;
    int p = atomicAdd(&cursor[d], 1);
    perm[p] = s;
}

// ===================== gathers (atomic-free segment sum) =====================
// One warp per dst node: out[d] = sum_{j in [rowptr[d],rowptr[d+1])} Y[perm[j]]

// fp32 messages (layer 0): lane reads float4 (512B/row total)
__global__ __launch_bounds__(256) void gather_f32(
    const float* __restrict__ Y, const int* __restrict__ rowptr,
    const int* __restrict__ perm, float* __restrict__ out, int n)
{
    int w    = (int)((blockIdx.x * (unsigned)blockDim.x + threadIdx.x) >> 5);
    int lane = threadIdx.x & 31;
    if (w >= n) return;

    int beg = __ldg(rowptr + w);
    int end = __ldg(rowptr + w + 1);

    const float4* Yv = reinterpret_cast<const float4*>(Y);
    float4 acc = make_float4(0.f, 0.f, 0.f, 0.f);

    for (int j0 = beg; j0 < end; j0 += 32) {
        int j  = j0 + lane;
        int sl = (j < end) ? __ldg(perm + j) : 0;
        int m  = min(32, end - j0);
        for (int t = 0; t < m; t++) {
            int s = __shfl_sync(0xffffffffu, sl, t);
            float4 v = Yv[(size_t)s * 32 + lane];
            acc.x += v.x; acc.y += v.y; acc.z += v.z; acc.w += v.w;
        }
    }
    reinterpret_cast<float4*>(out)[(size_t)w * 32 + lane] = acc;
}

// fp16 messages (final layer): lane reads uint2 = 4 halves (256B/row total)
__global__ __launch_bounds__(256) void gather_f16(
    const __half* __restrict__ Y, const int* __restrict__ rowptr,
    const int* __restrict__ perm, float* __restrict__ out, int n)
{
    int w    = (int)((blockIdx.x * (unsigned)blockDim.x + threadIdx.x) >> 5);
    int lane = threadIdx.x & 31;
    if (w >= n) return;

    int beg = __ldg(rowptr + w);
    int end = __ldg(rowptr + w + 1);

    const uint2* Yv = reinterpret_cast<const uint2*>(Y);  // 4 halves per lane
    float4 acc = make_float4(0.f, 0.f, 0.f, 0.f);

    for (int j0 = beg; j0 < end; j0 += 32) {
        int j  = j0 + lane;
        int sl = (j < end) ? __ldg(perm + j) : 0;
        int m  = min(32, end - j0);
        for (int t = 0; t < m; t++) {
            int s = __shfl_sync(0xffffffffu, sl, t);
            uint2 u = Yv[(size_t)s * 32 + lane];
            float2 a = __half22float2(*reinterpret_cast<__half2*>(&u.x));
            float2 b = __half22float2(*reinterpret_cast<__half2*>(&u.y));
            acc.x += a.x; acc.y += a.y; acc.z += b.x; acc.w += b.y;
        }
    }
    reinterpret_cast<float4*>(out)[(size_t)w * 32 + lane] = acc;
}

// ===================== 3xBF16 tensor-core GEMM =====================
//   Y[n_rows,128] = relu(X[n_rows,128] @ W[128,128] + b)
// CTA 128x128, 8 warps (2x4), warp tile 64x32, mma.m16n8k16.bf16.
// fp32 operands split once into bf16 hi/lo during staging, stored as packed
// bf16x2 u32 planes with stride 36 (bank = 4*gid+tig = lane, conflict-free).
// OUT_HALF: write Y as fp16 (final-layer messages, positive, sum-only use).
#define PS2 36

__device__ __forceinline__ uint32_t pack2(__nv_bfloat16 lo, __nv_bfloat16 hi)
{
    return (uint32_t)__bfloat16_as_ushort(lo) | ((uint32_t)__bfloat16_as_ushort(hi) << 16);
}

__device__ __forceinline__ void split2(float x, float y, uint32_t& h, uint32_t& l)
{
    __nv_bfloat16 hx = __float2bfloat16_rn(x);
    __nv_bfloat16 hy = __float2bfloat16_rn(y);
    __nv_bfloat16 lx = __float2bfloat16_rn(x - __bfloat162float(hx));
    __nv_bfloat16 ly = __float2bfloat16_rn(y - __bfloat162float(hy));
    h = pack2(hx, hy);
    l = pack2(lx, ly);
}

__device__ __forceinline__ void mma_bf16(float c[4], const uint32_t a[4], const uint32_t b[2])
{
    asm volatile(
        "mma.sync.aligned.m16n8k16.row.col.f32.bf16.bf16.f32 "
        "{%0,%1,%2,%3}, {%4,%5,%6,%7}, {%8,%9}, {%0,%1,%2,%3};"
        : "+f"(c[0]), "+f"(c[1]), "+f"(c[2]), "+f"(c[3])
        : "r"(a[0]), "r"(a[1]), "r"(a[2]), "r"(a[3]), "r"(b[0]), "r"(b[1]));
}

template <bool OUT_HALF>
__global__ __launch_bounds__(256, 2) void gemm_bf16x3(
    const float* __restrict__ X, const float* __restrict__ W,
    const float* __restrict__ bias, float* __restrict__ Yf,
    __half* __restrict__ Yh, int n_rows)
{
    extern __shared__ uint32_t sh[];
    uint32_t* Xh = sh;                 // [128][PS2]  X chunk hi (bf16x2)
    uint32_t* Xl = Xh + 128 * PS2;     // [128][PS2]  X chunk lo
    uint32_t* Wh = Xl + 128 * PS2;     // [n=128][PS2] W^T chunk hi
    uint32_t* Wl = Wh + 128 * PS2;     // [n=128][PS2] W^T chunk lo

    const int tid  = threadIdx.x;
    const int lane = tid & 31;
    const int gid  = lane >> 2;
    const int tig  = lane & 3;
    const int wid  = tid >> 5;
    const int wm   = wid & 1;
    const int wn   = wid >> 1;
    const int row0 = blockIdx.x * 128;

    float c[4][4][4];
#pragma unroll
    for (int i = 0; i < 4; i++)
#pragma unroll
        for (int j = 0; j < 4; j++)
#pragma unroll
            for (int q = 0; q < 4; q++) c[i][j][q] = 0.f;

#pragma unroll
    for (int kc = 0; kc < 2; kc++) {
        const int k0 = kc * 64;
        if (kc) __syncthreads();

        // ---- stage X chunk: 128 rows x 16 float4, split once ----
#pragma unroll
        for (int t = 0; t < 8; t++) {
            int idx = tid + t * 256;           // 0..2047
            int r   = idx >> 4;                // 0..127
            int c4  = (idx & 15) << 2;         // 0..60
            float4 v = make_float4(0.f, 0.f, 0.f, 0.f);
            if (row0 + r < n_rows)
                v = *reinterpret_cast<const float4*>(X + (size_t)(row0 + r) * DD + k0 + c4);
            int kp = c4 >> 1;
            uint32_t h, l;
            split2(v.x, v.y, h, l); Xh[r * PS2 + kp]     = h; Xl[r * PS2 + kp]     = l;
            split2(v.z, v.w, h, l); Xh[r * PS2 + kp + 1] = h; Xl[r * PS2 + kp + 1] = l;
        }
        // ---- stage W^T chunk: task (n, kp), coalesced over n ----
#pragma unroll
        for (int t = 0; t < 16; t++) {
            int idx = tid + t * 256;           // 0..4095
            int n   = idx & 127;
            int kp  = idx >> 7;                // 0..31
            int k   = k0 + 2 * kp;
            float w0 = W[(size_t)k * DD + n];
            float w1 = W[(size_t)(k + 1) * DD + n];
            uint32_t h, l;
            split2(w0, w1, h, l);
            Wh[n * PS2 + kp] = h;
            Wl[n * PS2 + kp] = l;
        }
        __syncthreads();

        // ---- compute: 4 k16-steps per chunk ----
#pragma unroll
        for (int ks = 0; ks < 4; ks++) {
            const int kb = ks * 8;

            uint32_t bh[4][2], bl[4][2];
#pragma unroll
            for (int nf = 0; nf < 4; nf++) {
                int n = wn * 32 + nf * 8 + gid;
                bh[nf][0] = Wh[n * PS2 + kb + tig];
                bh[nf][1] = Wh[n * PS2 + kb + tig + 4];
                bl[nf][0] = Wl[n * PS2 + kb + tig];
                bl[nf][1] = Wl[n * PS2 + kb + tig + 4];
            }
#pragma unroll
            for (int mf = 0; mf < 4; mf++) {
                int r0 = wm * 64 + mf * 16 + gid;
                uint32_t ah[4], al[4];
                ah[0] = Xh[r0 * PS2 + kb + tig];
                ah[1] = Xh[(r0 + 8) * PS2 + kb + tig];
                ah[2] = Xh[r0 * PS2 + kb + tig + 4];
                ah[3] = Xh[(r0 + 8) * PS2 + kb + tig + 4];
                al[0] = Xl[r0 * PS2 + kb + tig];
                al[1] = Xl[(r0 + 8) * PS2 + kb + tig];
                al[2] = Xl[r0 * PS2 + kb + tig + 4];
                al[3] = Xl[(r0 + 8) * PS2 + kb + tig + 4];
#pragma unroll
                for (int nf = 0; nf < 4; nf++) {
                    mma_bf16(c[mf][nf], al, bh[nf]);
                    mma_bf16(c[mf][nf], ah, bl[nf]);
                    mma_bf16(c[mf][nf], ah, bh[nf]);
                }
            }
        }
    }

    // ---- epilogue: bias + ReLU ----
#pragma unroll
    for (int nf = 0; nf < 4; nf++) {
        int col = wn * 32 + nf * 8 + 2 * tig;
        float2 bb = *reinterpret_cast<const float2*>(bias + col);
#pragma unroll
        for (int mf = 0; mf < 4; mf++) {
            int row = row0 + wm * 64 + mf * 16 + gid;
            if (row < n_rows) {
                float ox = fmaxf(c[mf][nf][0] + bb.x, 0.f);
                float oy = fmaxf(c[mf][nf][1] + bb.y, 0.f);
                if (OUT_HALF)
                    *reinterpret_cast<__half2*>(Yh + (size_t)row * DD + col) =
                        __floats2half2_rn(ox, oy);
                else
                    *reinterpret_cast<float2*>(Yf + (size_t)row * DD + col) =
                        make_float2(ox, oy);
            }
            if (row + 8 < n_rows) {
                float ox = fmaxf(c[mf][nf][2] + bb.x, 0.f);
                float oy = fmaxf(c[mf][nf][3] + bb.y, 0.f);
                if (OUT_HALF)
                    *reinterpret_cast<__half2*>(Yh + (size_t)(row + 8) * DD + col) =
                        __floats2half2_rn(ox, oy);
                else
                    *reinterpret_cast<float2*>(Yf + (size_t)(row + 8) * DD + col) =
                        make_float2(ox, oy);
            }
        }
    }
}

// ===================== launch =====================
extern "C" void kernel_launch(void* const* d_in, const int* in_sizes, int n_in,
                              void* d_out, int out_size)
{
    const float* x_user = nullptr;
    const int*   ei_f   = nullptr;
    const int*   ei_r   = nullptr;
    const float* Wm[4]  = {nullptr, nullptr, nullptr, nullptr};
    const float* bm[4]  = {nullptr, nullptr, nullptr, nullptr};
    int xcnt = 0, ecnt = 0, wcnt = 0, bcnt = 0;

    for (int i = 0; i < n_in; i++) {
        int sz = in_sizes[i];
        if (sz == NN * DD) {
            if (xcnt == 0) x_user = (const float*)d_in[i];
            xcnt++;                        // x_item is dead code in the reference
        } else if (sz == 2 * EE) {
            if (ecnt == 0) ei_f = (const int*)d_in[i];
            else           ei_r = (const int*)d_in[i];
            ecnt++;
        } else if (sz == DD * DD) {
            if (wcnt < 4) Wm[wcnt] = (const float*)d_in[i];
            wcnt++;
        } else if (sz == DD) {
            if (bcnt < 4) bm[bcnt] = (const float*)d_in[i];
            bcnt++;
        }
    }

    float  *yf, *u1;
    __half *yh_f, *yh_r;
    cudaGetSymbolAddress((void**)&yf,   g_yf);
    cudaGetSymbolAddress((void**)&yh_f, g_yh_f);
    cudaGetSymbolAddress((void**)&yh_r, g_yh_r);
    cudaGetSymbolAddress((void**)&u1,   g_u1);
    int *cnt, *rp, *pm, *pt;
    cudaGetSymbolAddress((void**)&cnt, g_cnt);
    cudaGetSymbolAddress((void**)&rp,  g_rowptr);
    cudaGetSymbolAddress((void**)&pm,  g_perm);
    cudaGetSymbolAddress((void**)&pt,  g_part);

    float* out_xu = (float*)d_out;
    float* out_xi = (float*)d_out + (size_t)NN * DD;

    const int* src_f = ei_f;
    const int* dst_f = ei_f + EE;
    const int* src_r = ei_r;
    const int* dst_r = ei_r + EE;

    const int eb2 = (2 * EE + 255) / 256;
    const int gb  = (NN + 7) / 8;             // one warp per node
    const int gemm_blocks = (NN + 127) / 128;
    const size_t gemm_smem = 4u * 128u * PS2 * sizeof(uint32_t);  // 73728 B

    static bool attr_set = false;
    if (!attr_set) {
        cudaFuncSetAttribute(gemm_bf16x3<false>,
                             cudaFuncAttributeMaxDynamicSharedMemorySize, (int)gemm_smem);
        cudaFuncSetAttribute(gemm_bf16x3<true>,
                             cudaFuncAttributeMaxDynamicSharedMemorySize, (int)gemm_smem);
        attr_set = true;
    }

    // ---- combined CSC build (both relations, single pipeline) ----
    cudaMemsetAsync(cnt, 0, 2u * NN * sizeof(int), 0);
    hist2_kernel<<<eb2, 256>>>(dst_f, dst_r, cnt);
    block_reduce<<<NB2, 1024>>>(cnt, pt, 2 * NN);
    scan_partials<<<1, 256>>>(pt, NB2);
    block_scan_write<<<NB2, 1024>>>(cnt, pt, rp, cnt, 2 * NN, 2 * EE);
    fill2_kernel<<<eb2, 256>>>(src_f, dst_f, src_r, dst_r, cnt, pm);

    // ---- layer 0 ('follows' only is live): u1 = segsum_f(relu(x @ W0f + b0f)) ----
    gemm_bf16x3<false><<<gemm_blocks, 256, gemm_smem>>>(
        x_user, Wm[0], bm[0], yf, nullptr, NN);
    gather_f32<<<gb, 256>>>(yf, rp, pm, u1, NN);

    // ---- layer 1 'follows' (fp16 messages) ----
    gemm_bf16x3<true><<<gemm_blocks, 256, gemm_smem>>>(
        u1, Wm[2], bm[2], nullptr, yh_f, NN);
    gather_f16<<<gb, 256>>>(yh_f, rp, pm, out_xu, NN);

    // ---- layer 1 'rates' (fp16 messages) ----
    gemm_bf16x3<true><<<gemm_blocks, 256, gemm_smem>>>(
        u1, Wm[3], bm[3], nullptr, yh_r, NN);
    gather_f16<<<gb, 256>>>(yh_r, rp + NN, pm, out_xi, NN);
}

// round 9
// speedup vs baseline: 1.1074x; 1.0144x over previous
#include <cuda_runtime.h>
#include <cuda_bf16.h>
#include <cuda_fp16.h>
#include <cstdint>

#define NN 100000   // nodes per type
#define EE 600000   // edges per relation
#define DD 128      // hidden dim
#define NB2 196     // scan blocks: ceil(2*NN/1024)

// ---------------- scratch (static device globals) ----------------
__device__ __half g_y0[(size_t)NN * DD];    // layer-0 messages (fp16)
__device__ __half g_yh_f[(size_t)NN * DD];  // layer-1 'follows' messages (fp16)
__device__ __half g_yh_r[(size_t)NN * DD];  // layer-1 'rates' messages (fp16)
__device__ float  g_u1[(size_t)NN * DD];    // layer-0 user output (fp32)
__device__ int    g_cnt[2 * NN];            // combined histogram / cursor
__device__ int    g_rowptr[2 * NN + 1];     // combined CSC row pointers
__device__ int    g_perm[2 * EE];           // src ids sorted by (rel,dst)
__device__ int    g_part[NB2];              // scan partials

// ===================== combined CSC build (both relations) =====================
__global__ void hist2_kernel(const int* __restrict__ dst_f, const int* __restrict__ dst_r,
                             int* __restrict__ cnt)
{
    int e = blockIdx.x * blockDim.x + threadIdx.x;
    if (e < EE)            atomicAdd(&cnt[dst_f[e]], 1);
    else if (e < 2 * EE)   atomicAdd(&cnt[NN + dst_r[e - EE]], 1);
}

__global__ __launch_bounds__(1024) void block_reduce(
    const int* __restrict__ cnt, int* __restrict__ part, int n)
{
    __shared__ int s[1024];
    int t = threadIdx.x;
    int idx = blockIdx.x * 1024 + t;
    s[t] = (idx < n) ? cnt[idx] : 0;
    __syncthreads();
#pragma unroll
    for (int off = 512; off > 0; off >>= 1) {
        if (t < off) s[t] += s[t + off];
        __syncthreads();
    }
    if (t == 0) part[blockIdx.x] = s[0];
}

__global__ __launch_bounds__(256) void scan_partials(int* __restrict__ part, int nb)
{
    __shared__ int s[256];
    int t = threadIdx.x;
    int v = (t < nb) ? part[t] : 0;
    s[t] = v;
    __syncthreads();
#pragma unroll
    for (int off = 1; off < 256; off <<= 1) {
        int x = (t >= off) ? s[t - off] : 0;
        __syncthreads();
        s[t] += x;
        __syncthreads();
    }
    if (t < nb) part[t] = s[t] - v;   // exclusive
}

__global__ __launch_bounds__(1024) void block_scan_write(
    const int* __restrict__ cnt, const int* __restrict__ part,
    int* __restrict__ rowptr, int* __restrict__ cursor, int n, int total)
{
    __shared__ int s[1024];
    int t = threadIdx.x;
    int idx = blockIdx.x * 1024 + t;
    int v = (idx < n) ? cnt[idx] : 0;
    s[t] = v;
    __syncthreads();
#pragma unroll
    for (int off = 1; off < 1024; off <<= 1) {
        int x = (t >= off) ? s[t - off] : 0;
        __syncthreads();
        s[t] += x;
        __syncthreads();
    }
    int excl = s[t] - v + part[blockIdx.x];
    if (idx < n) { rowptr[idx] = excl; cursor[idx] = excl; }
    if (idx == 0) rowptr[n] = total;
}

__global__ void fill2_kernel(const int* __restrict__ src_f, const int* __restrict__ dst_f,
                             const int* __restrict__ src_r, const int* __restrict__ dst_r,
                             int* __restrict__ cursor, int* __restrict__ perm)
{
    int e = blockIdx.x * blockDim.x + threadIdx.x;
    int s, d;
    if (e < EE)          { s = src_f[e];      d = dst_f[e]; }
    else if (e < 2 * EE) { s = src_r[e - EE]; d = NN + dst_r[e - EE]; }
    else return;
    int p = atomicAdd(&cursor[d], 1);
    perm[p] = s;
}

// ===================== gather (fp16 messages -> fp32 sums) =====================
// One warp per dst node: out[d] = sum_{j in [rowptr[d],rowptr[d+1])} Y[perm[j]]
__global__ __launch_bounds__(256) void gather_f16(
    const __half* __restrict__ Y, const int* __restrict__ rowptr,
    const int* __restrict__ perm, float* __restrict__ out, int n)
{
    int w    = (int)((blockIdx.x * (unsigned)blockDim.x + threadIdx.x) >> 5);
    int lane = threadIdx.x & 31;
    if (w >= n) return;

    int beg = __ldg(rowptr + w);
    int end = __ldg(rowptr + w + 1);

    const uint2* Yv = reinterpret_cast<const uint2*>(Y);  // 4 halves per lane
    float4 acc = make_float4(0.f, 0.f, 0.f, 0.f);

    for (int j0 = beg; j0 < end; j0 += 32) {
        int j  = j0 + lane;
        int sl = (j < end) ? __ldg(perm + j) : 0;
        int m  = min(32, end - j0);
        for (int t = 0; t < m; t++) {
            int s = __shfl_sync(0xffffffffu, sl, t);
            uint2 u = Yv[(size_t)s * 32 + lane];
            float2 a = __half22float2(*reinterpret_cast<__half2*>(&u.x));
            float2 b = __half22float2(*reinterpret_cast<__half2*>(&u.y));
            acc.x += a.x; acc.y += a.y; acc.z += b.x; acc.w += b.y;
        }
    }
    reinterpret_cast<float4*>(out)[(size_t)w * 32 + lane] = acc;
}

// ===================== 3xBF16 GEMM building blocks =====================
#define PS2 36

__device__ __forceinline__ uint32_t pack2(__nv_bfloat16 lo, __nv_bfloat16 hi)
{
    return (uint32_t)__bfloat16_as_ushort(lo) | ((uint32_t)__bfloat16_as_ushort(hi) << 16);
}

__device__ __forceinline__ void split2(float x, float y, uint32_t& h, uint32_t& l)
{
    __nv_bfloat16 hx = __float2bfloat16_rn(x);
    __nv_bfloat16 hy = __float2bfloat16_rn(y);
    __nv_bfloat16 lx = __float2bfloat16_rn(x - __bfloat162float(hx));
    __nv_bfloat16 ly = __float2bfloat16_rn(y - __bfloat162float(hy));
    h = pack2(hx, hy);
    l = pack2(lx, ly);
}

__device__ __forceinline__ void mma_bf16(float c[4], const uint32_t a[4], const uint32_t b[2])
{
    asm volatile(
        "mma.sync.aligned.m16n8k16.row.col.f32.bf16.bf16.f32 "
        "{%0,%1,%2,%3}, {%4,%5,%6,%7}, {%8,%9}, {%0,%1,%2,%3};"
        : "+f"(c[0]), "+f"(c[1]), "+f"(c[2]), "+f"(c[3])
        : "r"(a[0]), "r"(a[1]), "r"(a[2]), "r"(a[3]), "r"(b[0]), "r"(b[1]));
}

// ---- layer-0 GEMM: Y[n,128] = relu(X @ W + b), fp16 output ----
// 256 threads, 8 warps (2m x 4n), warp tile 64x32, 2 CTA/SM.
__global__ __launch_bounds__(256, 2) void gemm_l0(
    const float* __restrict__ X, const float* __restrict__ W,
    const float* __restrict__ bias, __half* __restrict__ Y, int n_rows)
{
    extern __shared__ uint32_t sh[];
    uint32_t* Xh = sh;
    uint32_t* Xl = Xh + 128 * PS2;
    uint32_t* Wh = Xl + 128 * PS2;
    uint32_t* Wl = Wh + 128 * PS2;

    const int tid  = threadIdx.x;
    const int lane = tid & 31;
    const int gid  = lane >> 2;
    const int tig  = lane & 3;
    const int wid  = tid >> 5;
    const int wm   = wid & 1;
    const int wn   = wid >> 1;
    const int row0 = blockIdx.x * 128;

    float c[4][4][4];
#pragma unroll
    for (int i = 0; i < 4; i++)
#pragma unroll
        for (int j = 0; j < 4; j++)
#pragma unroll
            for (int q = 0; q < 4; q++) c[i][j][q] = 0.f;

#pragma unroll
    for (int kc = 0; kc < 2; kc++) {
        const int k0 = kc * 64;
        if (kc) __syncthreads();

#pragma unroll
        for (int t = 0; t < 8; t++) {
            int idx = tid + t * 256;
            int r   = idx >> 4;
            int c4  = (idx & 15) << 2;
            float4 v = make_float4(0.f, 0.f, 0.f, 0.f);
            if (row0 + r < n_rows)
                v = *reinterpret_cast<const float4*>(X + (size_t)(row0 + r) * DD + k0 + c4);
            int kp = c4 >> 1;
            uint32_t h, l;
            split2(v.x, v.y, h, l); Xh[r * PS2 + kp]     = h; Xl[r * PS2 + kp]     = l;
            split2(v.z, v.w, h, l); Xh[r * PS2 + kp + 1] = h; Xl[r * PS2 + kp + 1] = l;
        }
#pragma unroll
        for (int t = 0; t < 16; t++) {
            int idx = tid + t * 256;
            int n   = idx & 127;
            int kp  = idx >> 7;
            int k   = k0 + 2 * kp;
            float w0 = W[(size_t)k * DD + n];
            float w1 = W[(size_t)(k + 1) * DD + n];
            uint32_t h, l;
            split2(w0, w1, h, l);
            Wh[n * PS2 + kp] = h;
            Wl[n * PS2 + kp] = l;
        }
        __syncthreads();

#pragma unroll
        for (int ks = 0; ks < 4; ks++) {
            const int kb = ks * 8;
            uint32_t bh[4][2], bl[4][2];
#pragma unroll
            for (int nf = 0; nf < 4; nf++) {
                int n = wn * 32 + nf * 8 + gid;
                bh[nf][0] = Wh[n * PS2 + kb + tig];
                bh[nf][1] = Wh[n * PS2 + kb + tig + 4];
                bl[nf][0] = Wl[n * PS2 + kb + tig];
                bl[nf][1] = Wl[n * PS2 + kb + tig + 4];
            }
#pragma unroll
            for (int mf = 0; mf < 4; mf++) {
                int r0 = wm * 64 + mf * 16 + gid;
                uint32_t ah[4], al[4];
                ah[0] = Xh[r0 * PS2 + kb + tig];
                ah[1] = Xh[(r0 + 8) * PS2 + kb + tig];
                ah[2] = Xh[r0 * PS2 + kb + tig + 4];
                ah[3] = Xh[(r0 + 8) * PS2 + kb + tig + 4];
                al[0] = Xl[r0 * PS2 + kb + tig];
                al[1] = Xl[(r0 + 8) * PS2 + kb + tig];
                al[2] = Xl[r0 * PS2 + kb + tig + 4];
                al[3] = Xl[(r0 + 8) * PS2 + kb + tig + 4];
#pragma unroll
                for (int nf = 0; nf < 4; nf++) {
                    mma_bf16(c[mf][nf], al, bh[nf]);
                    mma_bf16(c[mf][nf], ah, bl[nf]);
                    mma_bf16(c[mf][nf], ah, bh[nf]);
                }
            }
        }
    }

#pragma unroll
    for (int nf = 0; nf < 4; nf++) {
        int col = wn * 32 + nf * 8 + 2 * tig;
        float2 bb = *reinterpret_cast<const float2*>(bias + col);
#pragma unroll
        for (int mf = 0; mf < 4; mf++) {
            int row = row0 + wm * 64 + mf * 16 + gid;
            if (row < n_rows)
                *reinterpret_cast<__half2*>(Y + (size_t)row * DD + col) =
                    __floats2half2_rn(fmaxf(c[mf][nf][0] + bb.x, 0.f),
                                      fmaxf(c[mf][nf][1] + bb.y, 0.f));
            if (row + 8 < n_rows)
                *reinterpret_cast<__half2*>(Y + (size_t)(row + 8) * DD + col) =
                    __floats2half2_rn(fmaxf(c[mf][nf][2] + bb.x, 0.f),
                                      fmaxf(c[mf][nf][3] + bb.y, 0.f));
        }
    }
}

// ---- fused layer-1 GEMM: Yf = relu(X@Wf+bf), Yr = relu(X@Wr+br), fp16 out ----
// 512 threads, 16 warps (2m x 8n), warp tile 64x32, N=256 ([Wf | Wr]).
__global__ __launch_bounds__(512, 1) void gemm_l1_fused(
    const float* __restrict__ X,
    const float* __restrict__ Wf, const float* __restrict__ biasf,
    const float* __restrict__ Wr, const float* __restrict__ biasr,
    __half* __restrict__ Yf, __half* __restrict__ Yr, int n_rows)
{
    extern __shared__ uint32_t sh[];
    uint32_t* Xh = sh;                  // [128][PS2]
    uint32_t* Xl = Xh + 128 * PS2;
    uint32_t* Wh = Xl + 128 * PS2;      // [n=256][PS2]
    uint32_t* Wl = Wh + 256 * PS2;

    const int tid  = threadIdx.x;
    const int lane = tid & 31;
    const int gid  = lane >> 2;
    const int tig  = lane & 3;
    const int wid  = tid >> 5;
    const int wm   = wid & 1;
    const int wn   = wid >> 1;          // 0..7
    const int row0 = blockIdx.x * 128;

    float c[4][4][4];
#pragma unroll
    for (int i = 0; i < 4; i++)
#pragma unroll
        for (int j = 0; j < 4; j++)
#pragma unroll
            for (int q = 0; q < 4; q++) c[i][j][q] = 0.f;

#pragma unroll
    for (int kc = 0; kc < 2; kc++) {
        const int k0 = kc * 64;
        if (kc) __syncthreads();

        // stage X chunk: 2048 float4 tasks
#pragma unroll
        for (int t = 0; t < 4; t++) {
            int idx = tid + t * 512;
            int r   = idx >> 4;
            int c4  = (idx & 15) << 2;
            float4 v = make_float4(0.f, 0.f, 0.f, 0.f);
            if (row0 + r < n_rows)
                v = *reinterpret_cast<const float4*>(X + (size_t)(row0 + r) * DD + k0 + c4);
            int kp = c4 >> 1;
            uint32_t h, l;
            split2(v.x, v.y, h, l); Xh[r * PS2 + kp]     = h; Xl[r * PS2 + kp]     = l;
            split2(v.z, v.w, h, l); Xh[r * PS2 + kp + 1] = h; Xl[r * PS2 + kp + 1] = l;
        }
        // stage both W chunks: task (n 0..255, kp 0..31)
#pragma unroll
        for (int t = 0; t < 16; t++) {
            int idx = tid + t * 512;
            if (idx >= 256 * 32) break;
            int n   = idx & 255;
            int kp  = idx >> 8;
            int k   = k0 + 2 * kp;
            const float* Wsrc = (n < 128) ? Wf : Wr;
            int nn = n & 127;
            float w0 = Wsrc[(size_t)k * DD + nn];
            float w1 = Wsrc[(size_t)(k + 1) * DD + nn];
            uint32_t h, l;
            split2(w0, w1, h, l);
            Wh[n * PS2 + kp] = h;
            Wl[n * PS2 + kp] = l;
        }
        __syncthreads();

#pragma unroll
        for (int ks = 0; ks < 4; ks++) {
            const int kb = ks * 8;
            uint32_t bh[4][2], bl[4][2];
#pragma unroll
            for (int nf = 0; nf < 4; nf++) {
                int n = wn * 32 + nf * 8 + gid;
                bh[nf][0] = Wh[n * PS2 + kb + tig];
                bh[nf][1] = Wh[n * PS2 + kb + tig + 4];
                bl[nf][0] = Wl[n * PS2 + kb + tig];
                bl[nf][1] = Wl[n * PS2 + kb + tig + 4];
            }
#pragma unroll
            for (int mf = 0; mf < 4; mf++) {
                int r0 = wm * 64 + mf * 16 + gid;
                uint32_t ah[4], al[4];
                ah[0] = Xh[r0 * PS2 + kb + tig];
                ah[1] = Xh[(r0 + 8) * PS2 + kb + tig];
                ah[2] = Xh[r0 * PS2 + kb + tig + 4];
                ah[3] = Xh[(r0 + 8) * PS2 + kb + tig + 4];
                al[0] = Xl[r0 * PS2 + kb + tig];
                al[1] = Xl[(r0 + 8) * PS2 + kb + tig];
                al[2] = Xl[r0 * PS2 + kb + tig + 4];
                al[3] = Xl[(r0 + 8) * PS2 + kb + tig + 4];
#pragma unroll
                for (int nf = 0; nf < 4; nf++) {
                    mma_bf16(c[mf][nf], al, bh[nf]);
                    mma_bf16(c[mf][nf], ah, bl[nf]);
                    mma_bf16(c[mf][nf], ah, bh[nf]);
                }
            }
        }
    }

#pragma unroll
    for (int nf = 0; nf < 4; nf++) {
        int col = wn * 32 + nf * 8 + 2 * tig;   // 0..254
        bool isF = (col < 128);
        int ocol = isF ? col : (col - 128);
        const float* bsrc = isF ? biasf : biasr;
        __half* Ydst = isF ? Yf : Yr;
        float2 bb = *reinterpret_cast<const float2*>(bsrc + ocol);
#pragma unroll
        for (int mf = 0; mf < 4; mf++) {
            int row = row0 + wm * 64 + mf * 16 + gid;
            if (row < n_rows)
                *reinterpret_cast<__half2*>(Ydst + (size_t)row * DD + ocol) =
                    __floats2half2_rn(fmaxf(c[mf][nf][0] + bb.x, 0.f),
                                      fmaxf(c[mf][nf][1] + bb.y, 0.f));
            if (row + 8 < n_rows)
                *reinterpret_cast<__half2*>(Ydst + (size_t)(row + 8) * DD + ocol) =
                    __floats2half2_rn(fmaxf(c[mf][nf][2] + bb.x, 0.f),
                                      fmaxf(c[mf][nf][3] + bb.y, 0.f));
        }
    }
}

// ===================== launch =====================
extern "C" void kernel_launch(void* const* d_in, const int* in_sizes, int n_in,
                              void* d_out, int out_size)
{
    const float* x_user = nullptr;
    const int*   ei_f   = nullptr;
    const int*   ei_r   = nullptr;
    const float* Wm[4]  = {nullptr, nullptr, nullptr, nullptr};
    const float* bm[4]  = {nullptr, nullptr, nullptr, nullptr};
    int xcnt = 0, ecnt = 0, wcnt = 0, bcnt = 0;

    for (int i = 0; i < n_in; i++) {
        int sz = in_sizes[i];
        if (sz == NN * DD) {
            if (xcnt == 0) x_user = (const float*)d_in[i];
            xcnt++;                        // x_item is dead code in the reference
        } else if (sz == 2 * EE) {
            if (ecnt == 0) ei_f = (const int*)d_in[i];
            else           ei_r = (const int*)d_in[i];
            ecnt++;
        } else if (sz == DD * DD) {
            if (wcnt < 4) Wm[wcnt] = (const float*)d_in[i];
            wcnt++;
        } else if (sz == DD) {
            if (bcnt < 4) bm[bcnt] = (const float*)d_in[i];
            bcnt++;
        }
    }

    __half *y0, *yh_f, *yh_r;
    float  *u1;
    cudaGetSymbolAddress((void**)&y0,   g_y0);
    cudaGetSymbolAddress((void**)&yh_f, g_yh_f);
    cudaGetSymbolAddress((void**)&yh_r, g_yh_r);
    cudaGetSymbolAddress((void**)&u1,   g_u1);
    int *cnt, *rp, *pm, *pt;
    cudaGetSymbolAddress((void**)&cnt, g_cnt);
    cudaGetSymbolAddress((void**)&rp,  g_rowptr);
    cudaGetSymbolAddress((void**)&pm,  g_perm);
    cudaGetSymbolAddress((void**)&pt,  g_part);

    float* out_xu = (float*)d_out;
    float* out_xi = (float*)d_out + (size_t)NN * DD;

    const int* src_f = ei_f;
    const int* dst_f = ei_f + EE;
    const int* src_r = ei_r;
    const int* dst_r = ei_r + EE;

    const int eb2 = (2 * EE + 255) / 256;
    const int gb  = (NN + 7) / 8;
    const int gemm_blocks = (NN + 127) / 128;
    const size_t smem_l0 = 4u * 128u * PS2 * sizeof(uint32_t);           // 73728
    const size_t smem_l1 = (2u * 128u + 2u * 256u) * PS2 * sizeof(uint32_t); // 110592

    static cudaStream_t sB = nullptr;
    static cudaEvent_t  evFork = nullptr, evBuild = nullptr;
    static bool attr_set = false;
    if (!sB) {
        cudaStreamCreateWithFlags(&sB, cudaStreamNonBlocking);
        cudaEventCreateWithFlags(&evFork,  cudaEventDisableTiming);
        cudaEventCreateWithFlags(&evBuild, cudaEventDisableTiming);
    }
    if (!attr_set) {
        cudaFuncSetAttribute(gemm_l0, cudaFuncAttributeMaxDynamicSharedMemorySize,
                             (int)smem_l0);
        cudaFuncSetAttribute(gemm_l1_fused, cudaFuncAttributeMaxDynamicSharedMemorySize,
                             (int)smem_l1);
        attr_set = true;
    }

    // ---- fork: CSC build (L2/atomic-bound) overlapped with GEMM0 (tensor-bound) ----
    cudaEventRecord(evFork, 0);
    cudaStreamWaitEvent(sB, evFork, 0);

    cudaMemsetAsync(cnt, 0, 2u * NN * sizeof(int), sB);
    hist2_kernel<<<eb2, 256, 0, sB>>>(dst_f, dst_r, cnt);
    block_reduce<<<NB2, 1024, 0, sB>>>(cnt, pt, 2 * NN);
    scan_partials<<<1, 256, 0, sB>>>(pt, NB2);
    block_scan_write<<<NB2, 1024, 0, sB>>>(cnt, pt, rp, cnt, 2 * NN, 2 * EE);
    fill2_kernel<<<eb2, 256, 0, sB>>>(src_f, dst_f, src_r, dst_r, cnt, pm);
    cudaEventRecord(evBuild, sB);

    // ---- layer 0 ('follows' only is live): messages y0 = relu(x @ W0f + b0f) fp16
    gemm_l0<<<gemm_blocks, 256, smem_l0, 0>>>(x_user, Wm[0], bm[0], y0, NN);

    // join, then gather0 -> u1 (fp32)
    cudaStreamWaitEvent(0, evBuild, 0);
    gather_f16<<<gb, 256, 0, 0>>>(y0, rp, pm, u1, NN);

    // ---- layer 1: fused GEMM (N=256) writes both message sets fp16 ----
    gemm_l1_fused<<<gemm_blocks, 512, smem_l1, 0>>>(
        u1, Wm[2], bm[2], Wm[3], bm[3], yh_f, yh_r, NN);

    gather_f16<<<gb, 256, 0, 0>>>(yh_f, rp,      pm, out_xu, NN);
    gather_f16<<<gb, 256, 0, 0>>>(yh_r, rp + NN, pm, out_xi, NN);
}